// round 6
// baseline (speedup 1.0000x reference)
#include <cuda_runtime.h>
#include <cuda_bf16.h>

// Problem constants
#define B_     2
#define NC_    5
#define DHW_   2457600   // 96*160*160
#define N4_    (DHW_/4)  // 614400 float4 groups per (b, channel)
#define GRIDX_ 592
#define NBLK_  (GRIDX_ * B_)

// Scratch: [b][j], j: 0..19 = s_sum(k=j/4, ch=j%4+1), 20..39 = t_sum, 40..44 = nvox(k)
// Zero at module load; the last block re-zeros after consuming, so every
// invocation / graph replay starts from zeros.
__device__ double g_acc[B_][45];
__device__ unsigned int g_count = 0;

// exp(u) for tiny |u| via degree-6 Taylor (abs err << 1e-14 here); libm fallback.
__device__ __forceinline__ double fast_exp_small(double u) {
    if (fabs(u) > 0.125) return exp(u);
    double r = 1.0 / 720.0;
    r = fma(r, u, 1.0 / 120.0);
    r = fma(r, u, 1.0 / 24.0);
    r = fma(r, u, 1.0 / 6.0);
    r = fma(r, u, 0.5);
    r = fma(r, u, 1.0);
    r = fma(r, u, 1.0);
    return r;
}

// log(es) for es near 4: ln4 + 2*atanh(w), w = v/(2+v), v = (es-4)/4.
__device__ __forceinline__ double fast_log_near4(double es) {
    double v = (es - 4.0) * 0.25;
    if (fabs(v) > 0.125) return log(es);
    double w = v / (2.0 + v);
    double w2 = w * w;
    double r = 1.0 / 7.0;
    r = fma(r, w2, 1.0 / 5.0);
    r = fma(r, w2, 1.0 / 3.0);
    r = fma(r, w2, 1.0);
    return fma(2.0 * w, r, 1.3862943611198906188);  // + ln(4)
}

__global__ __launch_bounds__(256)
void kd_fused_kernel(const float* __restrict__ src,
                     const float* __restrict__ tgt,
                     const int* __restrict__ gt,
                     float* __restrict__ out) {
    const int b = blockIdx.y;

    // Register-private bins: 5 classes x 4 channels x {s,t} + 5 counts
    float accS[5][4], accT[5][4], accN[5];
#pragma unroll
    for (int i = 0; i < 5; i++) {
        accN[i] = 0.f;
#pragma unroll
        for (int c = 0; c < 4; c++) { accS[i][c] = 0.f; accT[i][c] = 0.f; }
    }

    const float* Sb = src + (size_t)b * NC_ * DHW_;
    const float* Tb = tgt + (size_t)b * NC_ * DHW_;
    const float4* s1p = (const float4*)(Sb + 1 * (size_t)DHW_);
    const float4* s2p = (const float4*)(Sb + 2 * (size_t)DHW_);
    const float4* s3p = (const float4*)(Sb + 3 * (size_t)DHW_);
    const float4* s4p = (const float4*)(Sb + 4 * (size_t)DHW_);
    const float4* t1p = (const float4*)(Tb + 1 * (size_t)DHW_);
    const float4* t2p = (const float4*)(Tb + 2 * (size_t)DHW_);
    const float4* t3p = (const float4*)(Tb + 3 * (size_t)DHW_);
    const float4* t4p = (const float4*)(Tb + 4 * (size_t)DHW_);
    const int4* g4 = (const int4*)(gt + (size_t)b * DHW_);

    const int stride = gridDim.x * blockDim.x;

    for (int i = blockIdx.x * blockDim.x + threadIdx.x; i < N4_; i += stride) {
        int4   g  = __ldcs(g4 + i);
        float4 s1 = __ldcs(s1p + i);
        float4 s2 = __ldcs(s2p + i);
        float4 s3 = __ldcs(s3p + i);
        float4 s4 = __ldcs(s4p + i);
        float4 t1 = __ldcs(t1p + i);
        float4 t2 = __ldcs(t2p + i);
        float4 t3 = __ldcs(t3p + i);
        float4 t4 = __ldcs(t4p + i);

#pragma unroll
        for (int k = 0; k < 5; k++) {
            float m;
            m = (g.x == k) ? 1.0f : 0.0f;
            accN[k]    += m;
            accS[k][0] += m * s1.x;  accS[k][1] += m * s2.x;
            accS[k][2] += m * s3.x;  accS[k][3] += m * s4.x;
            accT[k][0] += m * t1.x;  accT[k][1] += m * t2.x;
            accT[k][2] += m * t3.x;  accT[k][3] += m * t4.x;
            m = (g.y == k) ? 1.0f : 0.0f;
            accN[k]    += m;
            accS[k][0] += m * s1.y;  accS[k][1] += m * s2.y;
            accS[k][2] += m * s3.y;  accS[k][3] += m * s4.y;
            accT[k][0] += m * t1.y;  accT[k][1] += m * t2.y;
            accT[k][2] += m * t3.y;  accT[k][3] += m * t4.y;
            m = (g.z == k) ? 1.0f : 0.0f;
            accN[k]    += m;
            accS[k][0] += m * s1.z;  accS[k][1] += m * s2.z;
            accS[k][2] += m * s3.z;  accS[k][3] += m * s4.z;
            accT[k][0] += m * t1.z;  accT[k][1] += m * t2.z;
            accT[k][2] += m * t3.z;  accT[k][3] += m * t4.z;
            m = (g.w == k) ? 1.0f : 0.0f;
            accN[k]    += m;
            accS[k][0] += m * s1.w;  accS[k][1] += m * s2.w;
            accS[k][2] += m * s3.w;  accS[k][3] += m * s4.w;
            accT[k][0] += m * t1.w;  accT[k][1] += m * t2.w;
            accT[k][2] += m * t3.w;  accT[k][3] += m * t4.w;
        }
    }

    // ---- warp reduction ----
    const unsigned FULL = 0xffffffffu;
#pragma unroll
    for (int off = 16; off > 0; off >>= 1) {
#pragma unroll
        for (int i = 0; i < 5; i++) {
            accN[i] += __shfl_down_sync(FULL, accN[i], off);
#pragma unroll
            for (int c = 0; c < 4; c++) {
                accS[i][c] += __shfl_down_sync(FULL, accS[i][c], off);
                accT[i][c] += __shfl_down_sync(FULL, accT[i][c], off);
            }
        }
    }

    __shared__ float red[8][46];
    __shared__ bool is_last;
    const int w = threadIdx.x >> 5;
    const int lane = threadIdx.x & 31;
    if (lane == 0) {
#pragma unroll
        for (int i = 0; i < 5; i++) {
#pragma unroll
            for (int c = 0; c < 4; c++) {
                red[w][i * 4 + c]      = accS[i][c];
                red[w][20 + i * 4 + c] = accT[i][c];
            }
            red[w][40 + i] = accN[i];
        }
    }
    __syncthreads();

    if (threadIdx.x < 45) {
        float s = 0.f;
#pragma unroll
        for (int ww = 0; ww < 8; ww++) s += red[ww][threadIdx.x];
        atomicAdd(&g_acc[b][threadIdx.x], (double)s);
    }
    __syncthreads();

    // ---- last-block ticket: the final arriver runs the epilogue ----
    if (threadIdx.x == 0) {
        __threadfence();
        unsigned int old = atomicAdd(&g_count, 1u);
        is_last = (old == (unsigned)(NBLK_ - 1));
    }
    __syncthreads();
    if (!is_last) return;
    __threadfence();

    if (threadIdx.x < 32) {
        const int t = threadIdx.x;
        double my = 0.0;

        if (t < 10) {
            const int k = t >> 1;   // class
            const int bb = t & 1;   // batch

            // nvox summed over BOTH batches (onehot summed over axes 1..4,
            // axis 1 = batch), shared by both batches' averages.
            double nvox = g_acc[0][40 + k] + g_acc[1][40 + k];
            double inv = 1.0 / ((nvox + 1e-6) * 2.0);  // /(nvox+eps)/temperature

            double sl[4], tl[4];
#pragma unroll
            for (int c = 0; c < 4; c++) {
                sl[c] = g_acc[bb][k * 4 + c] * inv;
                tl[c] = g_acc[bb][20 + k * 4 + c] * inv;
            }
            double ms = sl[0], mt = tl[0];
#pragma unroll
            for (int c = 1; c < 4; c++) {
                if (sl[c] > ms) ms = sl[c];
                if (tl[c] > mt) mt = tl[c];
            }
            double esx[4], etx[4], es = 0.0, et = 0.0;
#pragma unroll
            for (int c = 0; c < 4; c++) {
                esx[c] = fast_exp_small(sl[c] - ms);
                etx[c] = fast_exp_small(tl[c] - mt);
                es += esx[c];
                et += etx[c];
            }
            double lses = ms + fast_log_near4(es);
            double lset = mt + fast_log_near4(et);
            double ies = 1.0 / es, iet = 1.0 / et;
#pragma unroll
            for (int c = 0; c < 4; c++) {
                double d = (tl[c] - lset) - (sl[c] - lses);  // tlp - slp
                my += (etx[c] * iet - esx[c] * ies) * d;     // pt*d + ps*(-d)
            }
        }

#pragma unroll
        for (int off = 16; off > 0; off >>= 1)
            my += __shfl_down_sync(FULL, my, off);

        if (t == 0) {
            // /batch(2) per KL, *0.5 pair average, mean over 5 classes => /20
            out[0] = (float)(my / 20.0);
            g_count = 0;
        }
        // Re-zero scratch for the next invocation / graph replay.
        double* p = (double*)g_acc;
        for (int j = t; j < B_ * 45; j += 32) p[j] = 0.0;
    }
}

extern "C" void kernel_launch(void* const* d_in, const int* in_sizes, int n_in,
                              void* d_out, int out_size) {
    const float* src = (const float*)d_in[0];
    const float* tgt = (const float*)d_in[1];
    const int* gt = (const int*)d_in[2];
    float* out = (float*)d_out;

    dim3 grid(GRIDX_, B_);
    kd_fused_kernel<<<grid, 256>>>(src, tgt, gt, out);
}

// round 7
// speedup vs baseline: 1.1345x; 1.1345x over previous
#include <cuda_runtime.h>
#include <cuda_bf16.h>

// Problem constants
#define B_     2
#define NC_    5
#define DHW_   2457600   // 96*160*160
#define N4_    (DHW_/4)  // 614400 float4 groups per (b, channel)
#define GRIDX_ 592
#define NBLK_  (GRIDX_ * 4)

// Scratch: [by][j], by = b*2 + h (h: 0=source, 1=target)
// j: 0..19 = sum(k=j/4, ch=j%4+1), 20..24 = voxel count per class (valid in h=0 halves)
// Zero at module load; the last block re-zeros after consuming.
__device__ double g_acc[4][25];
__device__ unsigned int g_count = 0;

// exp(u) for tiny |u| via degree-6 Taylor; libm fallback for robustness.
__device__ __forceinline__ double fast_exp_small(double u) {
    if (fabs(u) > 0.125) return exp(u);
    double r = 1.0 / 720.0;
    r = fma(r, u, 1.0 / 120.0);
    r = fma(r, u, 1.0 / 24.0);
    r = fma(r, u, 1.0 / 6.0);
    r = fma(r, u, 0.5);
    r = fma(r, u, 1.0);
    r = fma(r, u, 1.0);
    return r;
}

// log(es) for es near 4: ln4 + 2*atanh(w), w = v/(2+v), v = (es-4)/4.
__device__ __forceinline__ double fast_log_near4(double es) {
    double v = (es - 4.0) * 0.25;
    if (fabs(v) > 0.125) return log(es);
    double w = v / (2.0 + v);
    double w2 = w * w;
    double r = 1.0 / 7.0;
    r = fma(r, w2, 1.0 / 5.0);
    r = fma(r, w2, 1.0 / 3.0);
    r = fma(r, w2, 1.0);
    return fma(2.0 * w, r, 1.3862943611198906188);  // + ln(4)
}

__global__ __launch_bounds__(256)
void kd_fused_kernel(const float* __restrict__ src,
                     const float* __restrict__ tgt,
                     const int* __restrict__ gt,
                     float* __restrict__ out) {
    const int by = blockIdx.y;
    const int b = by >> 1;
    const int h = by & 1;

    // Register-private bins: 5 classes x 4 channels + 5 counts = 25 floats
    float acc[5][4], accN[5];
#pragma unroll
    for (int i = 0; i < 5; i++) {
        accN[i] = 0.f;
#pragma unroll
        for (int c = 0; c < 4; c++) acc[i][c] = 0.f;
    }

    const float* base = (h ? tgt : src) + (size_t)b * NC_ * DHW_;
    const float4* p1 = (const float4*)(base + 1 * (size_t)DHW_);
    const float4* p2 = (const float4*)(base + 2 * (size_t)DHW_);
    const float4* p3 = (const float4*)(base + 3 * (size_t)DHW_);
    const float4* p4 = (const float4*)(base + 4 * (size_t)DHW_);
    const int4* g4 = (const int4*)(gt + (size_t)b * DHW_);

    const int stride = gridDim.x * blockDim.x;

#pragma unroll 1
    for (int i = blockIdx.x * blockDim.x + threadIdx.x; i < N4_; i += stride) {
        int4   g  = __ldg(g4 + i);      // read twice across halves -> keep L2-cacheable
        float4 v1 = __ldcs(p1 + i);     // logits: read-once, stream
        float4 v2 = __ldcs(p2 + i);
        float4 v3 = __ldcs(p3 + i);
        float4 v4 = __ldcs(p4 + i);

#pragma unroll
        for (int k = 0; k < 5; k++) {
            float m;
            m = (g.x == k) ? 1.0f : 0.0f;
            accN[k]   += m;
            acc[k][0] += m * v1.x;  acc[k][1] += m * v2.x;
            acc[k][2] += m * v3.x;  acc[k][3] += m * v4.x;
            m = (g.y == k) ? 1.0f : 0.0f;
            accN[k]   += m;
            acc[k][0] += m * v1.y;  acc[k][1] += m * v2.y;
            acc[k][2] += m * v3.y;  acc[k][3] += m * v4.y;
            m = (g.z == k) ? 1.0f : 0.0f;
            accN[k]   += m;
            acc[k][0] += m * v1.z;  acc[k][1] += m * v2.z;
            acc[k][2] += m * v3.z;  acc[k][3] += m * v4.z;
            m = (g.w == k) ? 1.0f : 0.0f;
            accN[k]   += m;
            acc[k][0] += m * v1.w;  acc[k][1] += m * v2.w;
            acc[k][2] += m * v3.w;  acc[k][3] += m * v4.w;
        }
    }

    // ---- warp reduction (deterministic tree) ----
    const unsigned FULL = 0xffffffffu;
#pragma unroll
    for (int off = 16; off > 0; off >>= 1) {
#pragma unroll
        for (int i = 0; i < 5; i++) {
            accN[i] += __shfl_down_sync(FULL, accN[i], off);
#pragma unroll
            for (int c = 0; c < 4; c++)
                acc[i][c] += __shfl_down_sync(FULL, acc[i][c], off);
        }
    }

    __shared__ float red[8][26];
    __shared__ bool is_last;
    const int w = threadIdx.x >> 5;
    const int lane = threadIdx.x & 31;
    if (lane == 0) {
#pragma unroll
        for (int i = 0; i < 5; i++) {
#pragma unroll
            for (int c = 0; c < 4; c++) red[w][i * 4 + c] = acc[i][c];
            red[w][20 + i] = accN[i];
        }
    }
    __syncthreads();

    if (threadIdx.x < 25) {
        float s = 0.f;
#pragma unroll
        for (int ww = 0; ww < 8; ww++) s += red[ww][threadIdx.x];
        atomicAdd(&g_acc[by][threadIdx.x], (double)s);
    }
    __syncthreads();

    // ---- last-block ticket: the final arriver runs the epilogue ----
    if (threadIdx.x == 0) {
        __threadfence();
        unsigned int old = atomicAdd(&g_count, 1u);
        is_last = (old == (unsigned)(NBLK_ - 1));
    }
    __syncthreads();
    if (!is_last) return;
    __threadfence();

    if (threadIdx.x < 32) {
        const int t = threadIdx.x;
        double my = 0.0;

        if (t < 10) {
            const int k = t >> 1;   // class
            const int bb = t & 1;   // batch

            // nvox summed over BOTH batches (onehot summed over axes 1..4,
            // axis 1 = batch), shared by both batches' averages.
            // Counts live in the source halves (by = 0 and 2).
            double nvox = g_acc[0][20 + k] + g_acc[2][20 + k];
            double inv = 1.0 / ((nvox + 1e-6) * 2.0);  // /(nvox+eps)/temperature

            double sl[4], tl[4];
#pragma unroll
            for (int c = 0; c < 4; c++) {
                sl[c] = g_acc[bb * 2 + 0][k * 4 + c] * inv;
                tl[c] = g_acc[bb * 2 + 1][k * 4 + c] * inv;
            }
            double ms = sl[0], mt = tl[0];
#pragma unroll
            for (int c = 1; c < 4; c++) {
                if (sl[c] > ms) ms = sl[c];
                if (tl[c] > mt) mt = tl[c];
            }
            double esx[4], etx[4], es = 0.0, et = 0.0;
#pragma unroll
            for (int c = 0; c < 4; c++) {
                esx[c] = fast_exp_small(sl[c] - ms);
                etx[c] = fast_exp_small(tl[c] - mt);
                es += esx[c];
                et += etx[c];
            }
            double lses = ms + fast_log_near4(es);
            double lset = mt + fast_log_near4(et);
            double ies = 1.0 / es, iet = 1.0 / et;
#pragma unroll
            for (int c = 0; c < 4; c++) {
                double d = (tl[c] - lset) - (sl[c] - lses);  // tlp - slp
                my += (etx[c] * iet - esx[c] * ies) * d;     // pt*d - ps*d
            }
        }

#pragma unroll
        for (int off = 16; off > 0; off >>= 1)
            my += __shfl_down_sync(FULL, my, off);

        if (t == 0) {
            // /batch(2) per KL, *0.5 pair average, mean over 5 classes => /20
            out[0] = (float)(my / 20.0);
            g_count = 0;
        }
        // Re-zero scratch for the next invocation / graph replay.
        double* p = (double*)g_acc;
        for (int j = t; j < 4 * 25; j += 32) p[j] = 0.0;
    }
}

extern "C" void kernel_launch(void* const* d_in, const int* in_sizes, int n_in,
                              void* d_out, int out_size) {
    const float* src = (const float*)d_in[0];
    const float* tgt = (const float*)d_in[1];
    const int* gt = (const int*)d_in[2];
    float* out = (float*)d_out;

    dim3 grid(GRIDX_, 4);
    kd_fused_kernel<<<grid, 256>>>(src, tgt, gt, out);
}

// round 8
// speedup vs baseline: 1.1505x; 1.0141x over previous
#include <cuda_runtime.h>
#include <cuda_bf16.h>

// Problem constants
#define B_      2
#define NC_     5
#define DHW_    2457600            // 96*160*160
#define N4_     (DHW_/4)           // 614400 float4 groups per (b, channel)
#define GRIDX_  600
#define SLICE_  (GRIDX_ * 256)     // 153600 threads per (b,h) slice; N4_ = 4*SLICE_
#define NBLK_   (GRIDX_ * 4)

// Scratch: [by][j], by = b*2 + h (h: 0=source, 1=target)
// j: 0..15 = sum(k, ch) for k=0..3, ch index c=ch-1 (j = k*4+c)
//    16..19 = per-channel totals (all classes)   20..23 = counts k=0..3
// class-4 sums/counts are derived by subtraction in the epilogue.
__device__ double g_acc[4][24];
__device__ unsigned int g_count = 0;

// exp(u) for tiny |u| via degree-6 Taylor; libm fallback for robustness.
__device__ __forceinline__ double fast_exp_small(double u) {
    if (fabs(u) > 0.125) return exp(u);
    double r = 1.0 / 720.0;
    r = fma(r, u, 1.0 / 120.0);
    r = fma(r, u, 1.0 / 24.0);
    r = fma(r, u, 1.0 / 6.0);
    r = fma(r, u, 0.5);
    r = fma(r, u, 1.0);
    r = fma(r, u, 1.0);
    return r;
}

// log(es) for es near 4: ln4 + 2*atanh(w), w = v/(2+v), v = (es-4)/4.
__device__ __forceinline__ double fast_log_near4(double es) {
    double v = (es - 4.0) * 0.25;
    if (fabs(v) > 0.125) return log(es);
    double w = v / (2.0 + v);
    double w2 = w * w;
    double r = 1.0 / 7.0;
    r = fma(r, w2, 1.0 / 5.0);
    r = fma(r, w2, 1.0 / 3.0);
    r = fma(r, w2, 1.0);
    return fma(2.0 * w, r, 1.3862943611198906188);  // + ln(4)
}

__global__ __launch_bounds__(256, 3)
void kd_fused_kernel(const float* __restrict__ src,
                     const float* __restrict__ tgt,
                     const int* __restrict__ gt,
                     float* __restrict__ out) {
    const int by = blockIdx.y;
    const int b = by >> 1;
    const int h = by & 1;

    // Register bins: classes 0..3 x 4 channels, per-channel totals, counts 0..3
    float acc[4][4], accC[4], accN[4];
#pragma unroll
    for (int k = 0; k < 4; k++) {
        accN[k] = 0.f;
        accC[k] = 0.f;
#pragma unroll
        for (int c = 0; c < 4; c++) acc[k][c] = 0.f;
    }

    const float* base = (h ? tgt : src) + (size_t)b * NC_ * DHW_;
    const float4* p1 = (const float4*)(base + 1 * (size_t)DHW_);
    const float4* p2 = (const float4*)(base + 2 * (size_t)DHW_);
    const float4* p3 = (const float4*)(base + 3 * (size_t)DHW_);
    const float4* p4 = (const float4*)(base + 4 * (size_t)DHW_);
    const int4* g4 = (const int4*)(gt + (size_t)b * DHW_);

    const int tid0 = blockIdx.x * 256 + threadIdx.x;

    auto vox = [&](int g, float v1, float v2, float v3, float v4) {
        accC[0] += v1; accC[1] += v2; accC[2] += v3; accC[3] += v4;
#pragma unroll
        for (int k = 0; k < 4; k++) {
            float m = (g == k) ? 1.0f : 0.0f;
            accN[k]   += m;
            acc[k][0] += m * v1;
            acc[k][1] += m * v2;
            acc[k][2] += m * v3;
            acc[k][3] += m * v4;
        }
    };

#pragma unroll 1
    for (int j = 0; j < 2; j++) {
        const int ia = tid0 + j * (2 * SLICE_);
        const int ib = ia + SLICE_;
        // Front-batch all 10 loads for 2 voxel groups -> MLP 10/warp
        int4   ga = __ldg(g4 + ia);
        int4   gb = __ldg(g4 + ib);
        float4 a1 = __ldcs(p1 + ia);
        float4 a2 = __ldcs(p2 + ia);
        float4 a3 = __ldcs(p3 + ia);
        float4 a4 = __ldcs(p4 + ia);
        float4 b1 = __ldcs(p1 + ib);
        float4 b2 = __ldcs(p2 + ib);
        float4 b3 = __ldcs(p3 + ib);
        float4 b4 = __ldcs(p4 + ib);

        vox(ga.x, a1.x, a2.x, a3.x, a4.x);
        vox(ga.y, a1.y, a2.y, a3.y, a4.y);
        vox(ga.z, a1.z, a2.z, a3.z, a4.z);
        vox(ga.w, a1.w, a2.w, a3.w, a4.w);
        vox(gb.x, b1.x, b2.x, b3.x, b4.x);
        vox(gb.y, b1.y, b2.y, b3.y, b4.y);
        vox(gb.z, b1.z, b2.z, b3.z, b4.z);
        vox(gb.w, b1.w, b2.w, b3.w, b4.w);
    }

    // ---- warp reduction (deterministic tree), 24 values ----
    const unsigned FULL = 0xffffffffu;
#pragma unroll
    for (int off = 16; off > 0; off >>= 1) {
#pragma unroll
        for (int k = 0; k < 4; k++) {
            accN[k] += __shfl_down_sync(FULL, accN[k], off);
            accC[k] += __shfl_down_sync(FULL, accC[k], off);
#pragma unroll
            for (int c = 0; c < 4; c++)
                acc[k][c] += __shfl_down_sync(FULL, acc[k][c], off);
        }
    }

    __shared__ float red[8][25];
    __shared__ bool is_last;
    const int w = threadIdx.x >> 5;
    const int lane = threadIdx.x & 31;
    if (lane == 0) {
#pragma unroll
        for (int k = 0; k < 4; k++) {
#pragma unroll
            for (int c = 0; c < 4; c++) red[w][k * 4 + c] = acc[k][c];
            red[w][16 + k] = accC[k];
            red[w][20 + k] = accN[k];
        }
    }
    __syncthreads();

    if (threadIdx.x < 24) {
        float s = 0.f;
#pragma unroll
        for (int ww = 0; ww < 8; ww++) s += red[ww][threadIdx.x];
        atomicAdd(&g_acc[by][threadIdx.x], (double)s);
    }
    __syncthreads();

    // ---- last-block ticket: the final arriver runs the epilogue ----
    if (threadIdx.x == 0) {
        __threadfence();
        unsigned int old = atomicAdd(&g_count, 1u);
        is_last = (old == (unsigned)(NBLK_ - 1));
    }
    __syncthreads();
    if (!is_last) return;
    __threadfence();

    if (threadIdx.x < 32) {
        const int t = threadIdx.x;
        double my = 0.0;

        if (t < 10) {
            const int k = t >> 1;   // class 0..4
            const int bb = t & 1;   // batch

            // nvox summed over BOTH batches (onehot summed over axes 1..4,
            // axis 1 = batch), shared by both batches' averages. Counts live
            // in the source halves (by = 0 and 2); class 4 by subtraction.
            double n0 = g_acc[0][20] + g_acc[2][20];
            double n1 = g_acc[0][21] + g_acc[2][21];
            double n2 = g_acc[0][22] + g_acc[2][22];
            double n3 = g_acc[0][23] + g_acc[2][23];
            double nvox;
            if      (k == 0) nvox = n0;
            else if (k == 1) nvox = n1;
            else if (k == 2) nvox = n2;
            else if (k == 3) nvox = n3;
            else             nvox = 2.0 * (double)DHW_ - (n0 + n1 + n2 + n3);

            double inv = 1.0 / ((nvox + 1e-6) * 2.0);  // /(nvox+eps)/temperature

            const double* S = g_acc[bb * 2 + 0];
            const double* T = g_acc[bb * 2 + 1];
            double sl[4], tl[4];
#pragma unroll
            for (int c = 0; c < 4; c++) {
                double ssum, tsum;
                if (k < 4) {
                    ssum = S[k * 4 + c];
                    tsum = T[k * 4 + c];
                } else {
                    ssum = S[16 + c] - (S[c] + S[4 + c] + S[8 + c] + S[12 + c]);
                    tsum = T[16 + c] - (T[c] + T[4 + c] + T[8 + c] + T[12 + c]);
                }
                sl[c] = ssum * inv;
                tl[c] = tsum * inv;
            }
            double ms = sl[0], mt = tl[0];
#pragma unroll
            for (int c = 1; c < 4; c++) {
                if (sl[c] > ms) ms = sl[c];
                if (tl[c] > mt) mt = tl[c];
            }
            double esx[4], etx[4], es = 0.0, et = 0.0;
#pragma unroll
            for (int c = 0; c < 4; c++) {
                esx[c] = fast_exp_small(sl[c] - ms);
                etx[c] = fast_exp_small(tl[c] - mt);
                es += esx[c];
                et += etx[c];
            }
            double lses = ms + fast_log_near4(es);
            double lset = mt + fast_log_near4(et);
            double ies = 1.0 / es, iet = 1.0 / et;
#pragma unroll
            for (int c = 0; c < 4; c++) {
                double d = (tl[c] - lset) - (sl[c] - lses);  // tlp - slp
                my += (etx[c] * iet - esx[c] * ies) * d;     // pt*d - ps*d
            }
        }

#pragma unroll
        for (int off = 16; off > 0; off >>= 1)
            my += __shfl_down_sync(FULL, my, off);

        if (t == 0) {
            // /batch(2) per KL, *0.5 pair average, mean over 5 classes => /20
            out[0] = (float)(my / 20.0);
            g_count = 0;
        }
        // Re-zero scratch for the next invocation / graph replay.
        double* p = (double*)g_acc;
        for (int j = t; j < 4 * 24; j += 32) p[j] = 0.0;
    }
}

extern "C" void kernel_launch(void* const* d_in, const int* in_sizes, int n_in,
                              void* d_out, int out_size) {
    const float* src = (const float*)d_in[0];
    const float* tgt = (const float*)d_in[1];
    const int* gt = (const int*)d_in[2];
    float* out = (float*)d_out;

    dim3 grid(GRIDX_, 4);
    kd_fused_kernel<<<grid, 256>>>(src, tgt, gt, out);
}

// round 9
// speedup vs baseline: 1.2078x; 1.0498x over previous
#include <cuda_runtime.h>
#include <cuda_bf16.h>

// Problem constants
#define B_      2
#define NC_     5
#define DHW_    2457600            // 96*160*160
#define N4_     (DHW_/4)           // 614400 float4 groups per (b, channel)
#define GRIDX_  148
#define STRIDE_ (GRIDX_ * 256)     // 37888 threads per (b,h) slice
#define NBLK_   (GRIDX_ * 4)       // 592 blocks = 148 SMs x 4 CTAs: one wave

// Scratch: [by][j], by = b*2 + h (h: 0=source, 1=target)
// j: 0..15 = sum(k, ch) for k=0..3 (j = k*4 + c, c = ch-1)
//    16..19 = per-channel totals (all classes)   20..23 = counts k=0..3
// Class-4 sums/counts derived by subtraction in the epilogue.
__device__ double g_acc[4][24];
__device__ unsigned int g_count = 0;

typedef unsigned long long u64;

__device__ __forceinline__ u64 packf2(float lo, float hi) {
    u64 r;
    asm("mov.b64 %0, {%1, %2};" : "=l"(r) : "f"(lo), "f"(hi));
    return r;
}
__device__ __forceinline__ void unpackf2(u64 v, float& lo, float& hi) {
    asm("mov.b64 {%0, %1}, %2;" : "=f"(lo), "=f"(hi) : "l"(v));
}
__device__ __forceinline__ void addf2(u64& a, u64 b) {
    asm("add.rn.f32x2 %0, %0, %1;" : "+l"(a) : "l"(b));
}
// If (g == k): a01 += v01 (packed), a23 += v23 (packed), n += 1.0f
__device__ __forceinline__ void pred_acc(u64& a01, u64& a23, float& n,
                                         int g, int k, u64 v01, u64 v23) {
    asm("{\n\t"
        ".reg .pred p;\n\t"
        "setp.eq.s32 p, %3, %4;\n\t"
        "@p add.rn.f32x2 %0, %0, %5;\n\t"
        "@p add.rn.f32x2 %1, %1, %6;\n\t"
        "@p add.f32 %2, %2, 0f3F800000;\n\t"
        "}"
        : "+l"(a01), "+l"(a23), "+f"(n)
        : "r"(g), "r"(k), "l"(v01), "l"(v23));
}

// exp(u) for tiny |u| via degree-6 Taylor; libm fallback for robustness.
__device__ __forceinline__ double fast_exp_small(double u) {
    if (fabs(u) > 0.125) return exp(u);
    double r = 1.0 / 720.0;
    r = fma(r, u, 1.0 / 120.0);
    r = fma(r, u, 1.0 / 24.0);
    r = fma(r, u, 1.0 / 6.0);
    r = fma(r, u, 0.5);
    r = fma(r, u, 1.0);
    r = fma(r, u, 1.0);
    return r;
}

// log(es) for es near 4: ln4 + 2*atanh(w), w = v/(2+v), v = (es-4)/4.
__device__ __forceinline__ double fast_log_near4(double es) {
    double v = (es - 4.0) * 0.25;
    if (fabs(v) > 0.125) return log(es);
    double w = v / (2.0 + v);
    double w2 = w * w;
    double r = 1.0 / 7.0;
    r = fma(r, w2, 1.0 / 5.0);
    r = fma(r, w2, 1.0 / 3.0);
    r = fma(r, w2, 1.0);
    return fma(2.0 * w, r, 1.3862943611198906188);  // + ln(4)
}

__global__ __launch_bounds__(256, 4)
void kd_fused_kernel(const float* __restrict__ src,
                     const float* __restrict__ tgt,
                     const int* __restrict__ gt,
                     float* __restrict__ out) {
    const int by = blockIdx.y;
    const int b = by >> 1;
    const int h = by & 1;

    // Packed accumulators: acc01[k] = (ch1, ch2), acc23[k] = (ch3, ch4)
    u64 acc01[4], acc23[4], accC01, accC23;
    float accN[4];
#pragma unroll
    for (int k = 0; k < 4; k++) { acc01[k] = 0ull; acc23[k] = 0ull; accN[k] = 0.f; }
    accC01 = 0ull; accC23 = 0ull;

    const float* base = (h ? tgt : src) + (size_t)b * NC_ * DHW_;
    const float4* p1 = (const float4*)(base + 1 * (size_t)DHW_);
    const float4* p2 = (const float4*)(base + 2 * (size_t)DHW_);
    const float4* p3 = (const float4*)(base + 3 * (size_t)DHW_);
    const float4* p4 = (const float4*)(base + 4 * (size_t)DHW_);
    const int4* g4 = (const int4*)(gt + (size_t)b * DHW_);

    for (int i = blockIdx.x * 256 + threadIdx.x; i < N4_; i += STRIDE_) {
        int4   g  = __ldg(g4 + i);    // re-read across halves -> L2-cacheable
        float4 v1 = __ldcs(p1 + i);   // logits: read-once, stream
        float4 v2 = __ldcs(p2 + i);
        float4 v3 = __ldcs(p3 + i);
        float4 v4 = __ldcs(p4 + i);

        {
            u64 a = packf2(v1.x, v2.x), c = packf2(v3.x, v4.x);
            addf2(accC01, a); addf2(accC23, c);
#pragma unroll
            for (int k = 0; k < 4; k++) pred_acc(acc01[k], acc23[k], accN[k], g.x, k, a, c);
        }
        {
            u64 a = packf2(v1.y, v2.y), c = packf2(v3.y, v4.y);
            addf2(accC01, a); addf2(accC23, c);
#pragma unroll
            for (int k = 0; k < 4; k++) pred_acc(acc01[k], acc23[k], accN[k], g.y, k, a, c);
        }
        {
            u64 a = packf2(v1.z, v2.z), c = packf2(v3.z, v4.z);
            addf2(accC01, a); addf2(accC23, c);
#pragma unroll
            for (int k = 0; k < 4; k++) pred_acc(acc01[k], acc23[k], accN[k], g.z, k, a, c);
        }
        {
            u64 a = packf2(v1.w, v2.w), c = packf2(v3.w, v4.w);
            addf2(accC01, a); addf2(accC23, c);
#pragma unroll
            for (int k = 0; k < 4; k++) pred_acc(acc01[k], acc23[k], accN[k], g.w, k, a, c);
        }
    }

    // ---- unpack to 24 scalars ----
    float acc[4][4], accC[4];
#pragma unroll
    for (int k = 0; k < 4; k++) {
        unpackf2(acc01[k], acc[k][0], acc[k][1]);
        unpackf2(acc23[k], acc[k][2], acc[k][3]);
    }
    unpackf2(accC01, accC[0], accC[1]);
    unpackf2(accC23, accC[2], accC[3]);

    // ---- warp reduction (deterministic tree), 24 values ----
    const unsigned FULL = 0xffffffffu;
#pragma unroll
    for (int off = 16; off > 0; off >>= 1) {
#pragma unroll
        for (int k = 0; k < 4; k++) {
            accN[k] += __shfl_down_sync(FULL, accN[k], off);
            accC[k] += __shfl_down_sync(FULL, accC[k], off);
#pragma unroll
            for (int c = 0; c < 4; c++)
                acc[k][c] += __shfl_down_sync(FULL, acc[k][c], off);
        }
    }

    __shared__ float red[8][25];
    __shared__ bool is_last;
    const int w = threadIdx.x >> 5;
    const int lane = threadIdx.x & 31;
    if (lane == 0) {
#pragma unroll
        for (int k = 0; k < 4; k++) {
#pragma unroll
            for (int c = 0; c < 4; c++) red[w][k * 4 + c] = acc[k][c];
            red[w][16 + k] = accC[k];
            red[w][20 + k] = accN[k];
        }
    }
    __syncthreads();

    if (threadIdx.x < 24) {
        float s = 0.f;
#pragma unroll
        for (int ww = 0; ww < 8; ww++) s += red[ww][threadIdx.x];
        atomicAdd(&g_acc[by][threadIdx.x], (double)s);
    }
    __syncthreads();

    // ---- last-block ticket: the final arriver runs the epilogue ----
    if (threadIdx.x == 0) {
        __threadfence();
        unsigned int old = atomicAdd(&g_count, 1u);
        is_last = (old == (unsigned)(NBLK_ - 1));
    }
    __syncthreads();
    if (!is_last) return;
    __threadfence();

    if (threadIdx.x < 32) {
        const int t = threadIdx.x;
        double my = 0.0;

        if (t < 10) {
            const int k = t >> 1;   // class 0..4
            const int bb = t & 1;   // batch

            // nvox summed over BOTH batches (onehot summed over axes 1..4,
            // axis 1 = batch), shared by both batches' averages. Counts live
            // in the source halves (by = 0 and 2); class 4 by subtraction.
            double n0 = g_acc[0][20] + g_acc[2][20];
            double n1 = g_acc[0][21] + g_acc[2][21];
            double n2 = g_acc[0][22] + g_acc[2][22];
            double n3 = g_acc[0][23] + g_acc[2][23];
            double nvox;
            if      (k == 0) nvox = n0;
            else if (k == 1) nvox = n1;
            else if (k == 2) nvox = n2;
            else if (k == 3) nvox = n3;
            else             nvox = 2.0 * (double)DHW_ - (n0 + n1 + n2 + n3);

            double inv = 1.0 / ((nvox + 1e-6) * 2.0);  // /(nvox+eps)/temperature

            const double* S = g_acc[bb * 2 + 0];
            const double* T = g_acc[bb * 2 + 1];
            double sl[4], tl[4];
#pragma unroll
            for (int c = 0; c < 4; c++) {
                double ssum, tsum;
                if (k < 4) {
                    ssum = S[k * 4 + c];
                    tsum = T[k * 4 + c];
                } else {
                    ssum = S[16 + c] - (S[c] + S[4 + c] + S[8 + c] + S[12 + c]);
                    tsum = T[16 + c] - (T[c] + T[4 + c] + T[8 + c] + T[12 + c]);
                }
                sl[c] = ssum * inv;
                tl[c] = tsum * inv;
            }
            double ms = sl[0], mt = tl[0];
#pragma unroll
            for (int c = 1; c < 4; c++) {
                if (sl[c] > ms) ms = sl[c];
                if (tl[c] > mt) mt = tl[c];
            }
            double esx[4], etx[4], es = 0.0, et = 0.0;
#pragma unroll
            for (int c = 0; c < 4; c++) {
                esx[c] = fast_exp_small(sl[c] - ms);
                etx[c] = fast_exp_small(tl[c] - mt);
                es += esx[c];
                et += etx[c];
            }
            double lses = ms + fast_log_near4(es);
            double lset = mt + fast_log_near4(et);
            double ies = 1.0 / es, iet = 1.0 / et;
#pragma unroll
            for (int c = 0; c < 4; c++) {
                double d = (tl[c] - lset) - (sl[c] - lses);  // tlp - slp
                my += (etx[c] * iet - esx[c] * ies) * d;     // pt*d - ps*d
            }
        }

#pragma unroll
        for (int off = 16; off > 0; off >>= 1)
            my += __shfl_down_sync(FULL, my, off);

        if (t == 0) {
            // /batch(2) per KL, *0.5 pair average, mean over 5 classes => /20
            out[0] = (float)(my / 20.0);
            g_count = 0;
        }
        // Re-zero scratch for the next invocation / graph replay.
        double* p = (double*)g_acc;
        for (int j = t; j < 4 * 24; j += 32) p[j] = 0.0;
    }
}

extern "C" void kernel_launch(void* const* d_in, const int* in_sizes, int n_in,
                              void* d_out, int out_size) {
    const float* src = (const float*)d_in[0];
    const float* tgt = (const float*)d_in[1];
    const int* gt = (const int*)d_in[2];
    float* out = (float*)d_out;

    dim3 grid(GRIDX_, 4);
    kd_fused_kernel<<<grid, 256>>>(src, tgt, gt, out);
}